// round 15
// baseline (speedup 1.0000x reference)
#include <cuda_runtime.h>
#include <cuda_fp16.h>
#include <cstdint>

// ============================================================================
// EdgeFeatures: out[i] = (e[i] @ Us_w^T + Us_b) + Vx[src[i]] + Vx[dst[i]]
//   where Vx = x @ Vs_w^T + Vs_b
//
// Persistent-CTA single-pass fp16 GEMM, BM=128 x N-half=128:
//   2 CTAs/SM; each CTA owns one N-half (128 cols), B half (64 KB fp16) in
//   smem ONCE; loops over 128-row M-tiles with a cross-tile double-buffered
//   A pipeline. Warp tile 64x32 (64 MMAs/warp/chunk — R14's 32 was the
//   regression). A prefetch split into 2 batches to keep regs <= 128.
//
// NOTE: edge_index is int32 (JAX downcasts int64 with x64 disabled).
// NOTE: __device__ symbols referenced ONLY in device code (host-side decay
//       gives the host shadow address -> ATS-readable zeros on GB300).
// ============================================================================

#define HDIM 256
#define BM 128
#define BNH 128        // N-half per CTA
#define BK 64          // K elems per chunk
#define NCHUNK 4
#define NTHREADS 256   // 8 warps: 2 (M) x 4 (N); warp tile 64x32

// smem: B half (static) + 2 A stages
#define B_BYTES 65536          // 128 rows x 256 k fp16, 512 B/row
#define A_STAGE 16384          // 128 rows x 64 k fp16, 128 B/row
#define SMEM_ALLOC (B_BYTES + 2 * A_STAGE + 1024)

// -------------------------- device scratch ---------------------------------
__device__ float g_Vx[10112 * 256];               // Vx table (V <= 10112)
__device__ __half g_Whi[2][256 * 256];            // [0]=Us_w, [1]=Vs_w (fp16)

// -------------------------- helpers ----------------------------------------
__device__ __forceinline__ uint32_t smem_u32(const void* p) {
    uint32_t a;
    asm("{ .reg .u64 t; cvta.to.shared.u64 t, %1; cvt.u32.u64 %0, t; }"
        : "=r"(a) : "l"(p));
    return a;
}

// 128B-row swizzle (A stages)
__device__ __forceinline__ uint32_t sw128(uint32_t off) {
    return off ^ ((off >> 3) & 0x70);
}
// 512B-row swizzle (B half): row bits [11:9] XOR into bank bits [6:4]
__device__ __forceinline__ uint32_t sw512(uint32_t off) {
    return off ^ ((off >> 5) & 0x70);
}

__device__ __forceinline__ uint32_t packh(__half a, __half b) {
    return (uint32_t)__half_as_ushort(a) | ((uint32_t)__half_as_ushort(b) << 16);
}

#define LDSM4(r0, r1, r2, r3, addr) \
    asm volatile("ldmatrix.sync.aligned.m8n8.x4.shared.b16 {%0,%1,%2,%3}, [%4];" \
                 : "=r"(r0), "=r"(r1), "=r"(r2), "=r"(r3) : "r"(addr))

#define MMA16816(c, a, b0, b1) \
    asm volatile("mma.sync.aligned.m16n8k16.row.col.f32.f16.f16.f32 " \
                 "{%0,%1,%2,%3}, {%4,%5,%6,%7}, {%8,%9}, {%0,%1,%2,%3};" \
                 : "+f"((c)[0]), "+f"((c)[1]), "+f"((c)[2]), "+f"((c)[3]) \
                 : "r"((a)[0]), "r"((a)[1]), "r"((a)[2]), "r"((a)[3]), \
                   "r"(b0), "r"(b1))

#define CPASYNC16(dst, src) \
    asm volatile("cp.async.cg.shared.global [%0], [%1], 16;" \
                 :: "r"(dst), "l"(src))
#define CP_COMMIT() asm volatile("cp.async.commit_group;" ::: "memory")
#define CP_WAIT0()  asm volatile("cp.async.wait_group 0;" ::: "memory")

// -------------------------- weight conversion ------------------------------
__global__ void convert_weights_kernel(const float* __restrict__ us,
                                       const float* __restrict__ vs) {
    int i = blockIdx.x * blockDim.x + threadIdx.x;
    if (i < 256 * 256) {
        g_Whi[0][i] = __float2half_rn(us[i]);
        g_Whi[1][i] = __float2half_rn(vs[i]);
    }
}

// -------------------------- pipeline pieces --------------------------------
// A tile is 128 rows; loaded in two 64-row batches of 4 float4/thread.
__device__ __forceinline__ void prefetch_A_batch(const float* __restrict__ A,
                                                 int Mtot, int m0, int kc,
                                                 int half, int tid, float4* apf) {
    const int k0 = kc * BK;
    const int rbase = half * 64;
#pragma unroll
    for (int i = 0; i < 4; i++) {
        int q = tid + i * NTHREADS;     // 0..1023 (64 rows x 16 float4)
        int row = rbase + (q >> 4);
        int c4 = q & 15;
        if (m0 + row < Mtot)
            apf[i] = *(const float4*)(A + (size_t)(m0 + row) * HDIM + k0 + c4 * 4);
        else
            apf[i] = make_float4(0.f, 0.f, 0.f, 0.f);
    }
}

__device__ __forceinline__ void sts_A_batch(uint32_t stage, int half, int tid,
                                            const float4* apf) {
    const int rbase = half * 64;
#pragma unroll
    for (int i = 0; i < 4; i++) {
        int q = tid + i * NTHREADS;
        int row = rbase + (q >> 4);
        int c4 = q & 15;
        float4 a = apf[i];
        uint32_t h0 = packh(__float2half_rn(a.x), __float2half_rn(a.y));
        uint32_t h1 = packh(__float2half_rn(a.z), __float2half_rn(a.w));
        uint32_t off = sw128((uint32_t)(row * 128 + c4 * 8));
        asm volatile("st.shared.v2.u32 [%0], {%1,%2};"
                     :: "r"(stage + off), "r"(h0), "r"(h1));
    }
}

// Load the CTA's entire B half (128 rows x 256 k fp16) once.
__device__ __forceinline__ void cp_B_all(uint32_t bbase, int nhalf, int tid,
                                         const __half* __restrict__ Whi) {
#pragma unroll
    for (int i = 0; i < 16; i++) {
        int g = tid + i * NTHREADS;     // 0..4095: 128 rows x 32 granules
        int row = g >> 5;
        int gb = g & 31;
        uint32_t off = sw512((uint32_t)(row * 512 + gb * 16));
        CPASYNC16(bbase + off,
                  Whi + (size_t)(nhalf * BNH + row) * HDIM + gb * 8);
    }
}

// Two ks-steps of the chunk (ksh = 0 -> ks 0,1; ksh = 1 -> ks 2,3)
__device__ __forceinline__ void mma_half(uint32_t astage, uint32_t bbase, int kc,
                                         int ksh, int wm, int wn, int lid,
                                         float acc[4][4][4]) {
    const int lrow = (lid & 7) + ((lid >> 3) & 1) * 8;
    const int kb = ((lid >> 4) & 1) * 16;
#pragma unroll
    for (int k2 = 0; k2 < 2; k2++) {
        const int ks = ksh * 2 + k2;
        uint32_t ah[4][4];
#pragma unroll
        for (int mf = 0; mf < 4; mf++) {
            uint32_t off = sw128((uint32_t)((wm * 64 + mf * 16 + lrow) * 128 +
                                            ks * 32 + kb));
            LDSM4(ah[mf][0], ah[mf][1], ah[mf][2], ah[mf][3], astage + off);
        }
#pragma unroll
        for (int np = 0; np < 2; np++) {
            uint32_t boff = sw512((uint32_t)((wn * 32 + np * 16 + lrow) * 512 +
                                             kc * 128 + ks * 32 + kb));
            uint32_t bh0, bh1, bh2, bh3;
            LDSM4(bh0, bh1, bh2, bh3, bbase + boff);
#pragma unroll
            for (int mf = 0; mf < 4; mf++) {
                MMA16816(acc[mf][2 * np],     ah[mf], bh0, bh2);
                MMA16816(acc[mf][2 * np + 1], ah[mf], bh1, bh3);
            }
        }
    }
}

// -------------------------- main kernel ------------------------------------
// Persistent: bid&1 = N-half, (bid>>1) strides over 128-row M-tiles.
template <bool GATHER>
__global__ void __launch_bounds__(NTHREADS, 2)
edgefeat_kernel(const float* __restrict__ A, int Mtot, int widx,
                const float* __restrict__ bias,
                const int* __restrict__ eidx, int Etot,
                float* __restrict__ out_g)
{
    extern __shared__ char smem_raw[];
    const uint32_t base = (smem_u32(smem_raw) + 1023u) & ~1023u;
    const uint32_t bbase = base;
    const uint32_t astg[2] = { base + B_BYTES, base + B_BYTES + A_STAGE };

    const __half* __restrict__ Whi = g_Whi[widx];

    const int tid = threadIdx.x;
    const int wid = tid >> 5;
    const int lid = tid & 31;
    const int wm = wid & 1;            // 2 warps in M (64 rows each)
    const int wn = wid >> 1;           // 4 warps in N (32 cols each)
    const int nhalf = blockIdx.x & 1;
    const int mstep = gridDim.x >> 1;
    const int nmtiles = (Mtot + BM - 1) / BM;

    const int tq = lid & 3;
    const int trow = lid >> 2;
    const int cbase = nhalf * BNH + wn * 32;

    // static B half
    cp_B_all(bbase, nhalf, tid, Whi);
    CP_COMMIT();

    int mt = blockIdx.x >> 1;
    float4 apf[4];
    if (mt < nmtiles) {
        prefetch_A_batch(A, Mtot, mt * BM, 0, 0, tid, apf);
        sts_A_batch(astg[0], 0, tid, apf);
        prefetch_A_batch(A, Mtot, mt * BM, 0, 1, tid, apf);
        sts_A_batch(astg[0], 1, tid, apf);
    }
    CP_WAIT0();
    __syncthreads();

    // bias for this warp's columns (invariant across tiles)
    float2 biasr[4];
#pragma unroll
    for (int nf = 0; nf < 4; nf++)
        biasr[nf] = *(const float2*)(bias + cbase + nf * 8 + 2 * tq);

    int p = 0;
    while (mt < nmtiles) {
        const int m0 = mt * BM;
        const int mt_next = mt + mstep;

        float acc[4][4][4];
#pragma unroll
        for (int a = 0; a < 4; a++)
#pragma unroll
            for (int b = 0; b < 4; b++)
#pragma unroll
                for (int c = 0; c < 4; c++) acc[a][b][c] = 0.f;

#pragma unroll
        for (int kc = 0; kc < NCHUNK; kc++) {
            const bool last = (kc == NCHUNK - 1);
            const bool pf = !last || (mt_next < nmtiles);
            const int nm0 = last ? mt_next * BM : m0;
            const int nk  = last ? 0 : kc + 1;
            if (pf) prefetch_A_batch(A, Mtot, nm0, nk, 0, tid, apf);
            mma_half(astg[p], bbase, kc, 0, wm, wn, lid, acc);
            if (pf) {
                sts_A_batch(astg[p ^ 1], 0, tid, apf);
                prefetch_A_batch(A, Mtot, nm0, nk, 1, tid, apf);
            }
            mma_half(astg[p], bbase, kc, 1, wm, wn, lid, acc);
            if (pf) sts_A_batch(astg[p ^ 1], 1, tid, apf);
            __syncthreads();
            p ^= 1;
        }

        // epilogue (next tile's A chunk0 already prefetched + stored)
#pragma unroll
        for (int mf = 0; mf < 4; mf++) {
#pragma unroll
            for (int h = 0; h < 2; h++) {
                const int row = m0 + wm * 64 + mf * 16 + trow + 8 * h;
                if (row < Mtot) {
                    const float* vs = g_Vx;
                    const float* vd = g_Vx;
                    if (GATHER) {
                        vs = g_Vx + (size_t)eidx[row] * HDIM;
                        vd = g_Vx + (size_t)eidx[(size_t)Etot + row] * HDIM;
                    }
                    float* op = (GATHER ? out_g : g_Vx) + (size_t)row * HDIM;
#pragma unroll
                    for (int nf = 0; nf < 4; nf++) {
                        const int c = cbase + nf * 8 + 2 * tq;
                        float vx = acc[mf][nf][2 * h + 0] + biasr[nf].x;
                        float vy = acc[mf][nf][2 * h + 1] + biasr[nf].y;
                        if (GATHER) {
                            float2 s2 = *(const float2*)(vs + c);
                            float2 d2 = *(const float2*)(vd + c);
                            vx += s2.x + d2.x;
                            vy += s2.y + d2.y;
                        }
                        *(float2*)(op + c) = make_float2(vx, vy);
                    }
                }
            }
        }
        mt = mt_next;
    }
}

// -------------------------- launch -----------------------------------------
extern "C" void kernel_launch(void* const* d_in, const int* in_sizes, int n_in,
                              void* d_out, int out_size) {
    const float* x    = (const float*)d_in[0];
    const float* e    = (const float*)d_in[1];
    const int*   eidx = (const int*)d_in[2];      // int32! (JAX x64 disabled)
    const float* Us_w = (const float*)d_in[3];
    const float* Us_b = (const float*)d_in[4];
    const float* Vs_w = (const float*)d_in[5];
    const float* Vs_b = (const float*)d_in[6];
    float*       out  = (float*)d_out;

    const int V = in_sizes[0] / HDIM;   // 10000
    const int E = in_sizes[1] / HDIM;   // 300000

    int dev = 0, nsm = 148;
    cudaGetDevice(&dev);
    cudaDeviceGetAttribute(&nsm, cudaDevAttrMultiProcessorCount, dev);
    const int grid = 2 * nsm;           // 2 CTAs/SM, even (N-half pairs)

    cudaFuncSetAttribute(edgefeat_kernel<false>,
                         cudaFuncAttributeMaxDynamicSharedMemorySize, SMEM_ALLOC);
    cudaFuncSetAttribute(edgefeat_kernel<true>,
                         cudaFuncAttributeMaxDynamicSharedMemorySize, SMEM_ALLOC);

    convert_weights_kernel<<<256, 256>>>(Us_w, Vs_w);

    // Vx = x @ Vs_w^T + Vs_b  -> g_Vx   (weight set 1)
    edgefeat_kernel<false><<<grid, NTHREADS, SMEM_ALLOC>>>(
        x, V, 1, Vs_b, nullptr, 0, nullptr);

    // out = e @ Us_w^T + Us_b + Vx[src] + Vx[dst]   (weight set 0)
    edgefeat_kernel<true><<<grid, NTHREADS, SMEM_ALLOC>>>(
        e, E, 0, Us_b, eidx, E, out);
}

// round 16
// speedup vs baseline: 1.5077x; 1.5077x over previous
#include <cuda_runtime.h>
#include <cuda_fp16.h>
#include <cstdint>

// ============================================================================
// EdgeFeatures: out[i] = (e[i] @ Us_w^T + Us_b) + Vx[src[i]] + Vx[dst[i]]
//   where Vx = x @ Vs_w^T + Vs_b
//
// R13 winner structure (BM=64, BN=256, 8 warps 1x8, 2 CTAs/SM, double-
// buffered A regs + B cp.async) with the Vx table stored in fp16:
// gather L2 traffic 614MB -> 307MB, Vx writes halved. rel_err ~3.5e-4.
//
// NOTE: edge_index is int32 (JAX downcasts int64 with x64 disabled).
// NOTE: __device__ symbols referenced ONLY in device code (host-side decay
//       gives the host shadow address -> ATS-readable zeros on GB300).
// ============================================================================

#define HDIM 256
#define BM 64
#define BK 64          // K elems per chunk = 128 bytes of fp16 = SW128 atom row
#define NCHUNK 4       // 256 / 64
#define NTHREADS 256   // 8 warps: 1 (M) x 8 (N), 64x32 warp tile

// smem stage layout (offsets within one stage)
#define A_HI 0          // 64 x 64 fp16  = 8192 B
#define B_HI 8192       // 256 x 64 fp16 = 32768 B
#define STAGE_BYTES 40960
#define SMEM_ALLOC (2 * STAGE_BYTES + 1024)

// -------------------------- device scratch ---------------------------------
__device__ __half g_Vx[10112 * 256];              // Vx table, fp16 (V <= 10112)
__device__ __half g_Whi[2][256 * 256];            // [0]=Us_w, [1]=Vs_w (fp16)

// -------------------------- helpers ----------------------------------------
__device__ __forceinline__ uint32_t smem_u32(const void* p) {
    uint32_t a;
    asm("{ .reg .u64 t; cvta.to.shared.u64 t, %1; cvt.u32.u64 %0, t; }"
        : "=r"(a) : "l"(p));
    return a;
}

__device__ __forceinline__ uint32_t sw128(uint32_t off) {
    return off ^ ((off >> 3) & 0x70);
}

__device__ __forceinline__ uint32_t packh(__half a, __half b) {
    return (uint32_t)__half_as_ushort(a) | ((uint32_t)__half_as_ushort(b) << 16);
}

#define LDSM4(r0, r1, r2, r3, addr) \
    asm volatile("ldmatrix.sync.aligned.m8n8.x4.shared.b16 {%0,%1,%2,%3}, [%4];" \
                 : "=r"(r0), "=r"(r1), "=r"(r2), "=r"(r3) : "r"(addr))

#define MMA16816(c, a, b0, b1) \
    asm volatile("mma.sync.aligned.m16n8k16.row.col.f32.f16.f16.f32 " \
                 "{%0,%1,%2,%3}, {%4,%5,%6,%7}, {%8,%9}, {%0,%1,%2,%3};" \
                 : "+f"((c)[0]), "+f"((c)[1]), "+f"((c)[2]), "+f"((c)[3]) \
                 : "r"((a)[0]), "r"((a)[1]), "r"((a)[2]), "r"((a)[3]), \
                   "r"(b0), "r"(b1))

#define CPASYNC16(dst, src) \
    asm volatile("cp.async.cg.shared.global [%0], [%1], 16;" \
                 :: "r"(dst), "l"(src))
#define CP_COMMIT() asm volatile("cp.async.commit_group;" ::: "memory")
#define CP_WAIT0()  asm volatile("cp.async.wait_group 0;" ::: "memory")

// -------------------------- weight conversion ------------------------------
__global__ void convert_weights_kernel(const float* __restrict__ us,
                                       const float* __restrict__ vs) {
    int i = blockIdx.x * blockDim.x + threadIdx.x;
    if (i < 256 * 256) {
        g_Whi[0][i] = __float2half_rn(us[i]);
        g_Whi[1][i] = __float2half_rn(vs[i]);
    }
}

// -------------------------- pipeline pieces --------------------------------
__device__ __forceinline__ void prefetch_A(const float* __restrict__ A, int Mtot,
                                           int m0, int kc, int tid, float4* apf) {
    const int k0 = kc * BK;
#pragma unroll
    for (int i = 0; i < 4; i++) {
        int q = tid + i * NTHREADS;     // 0..1023 (64 rows x 16 float4)
        int row = q >> 4;
        int c4 = q & 15;
        if (m0 + row < Mtot)
            apf[i] = *(const float4*)(A + (size_t)(m0 + row) * HDIM + k0 + c4 * 4);
        else
            apf[i] = make_float4(0.f, 0.f, 0.f, 0.f);
    }
}

__device__ __forceinline__ void sts_A(uint32_t stage, int tid, const float4* apf) {
#pragma unroll
    for (int i = 0; i < 4; i++) {
        int q = tid + i * NTHREADS;
        int row = q >> 4;
        int c4 = q & 15;
        float4 a = apf[i];
        uint32_t h0 = packh(__float2half_rn(a.x), __float2half_rn(a.y));
        uint32_t h1 = packh(__float2half_rn(a.z), __float2half_rn(a.w));
        uint32_t off = sw128((uint32_t)(row * 128 + c4 * 8));
        asm volatile("st.shared.v2.u32 [%0], {%1,%2};"
                     :: "r"(stage + A_HI + off), "r"(h0), "r"(h1));
    }
}

__device__ __forceinline__ void cp_B(uint32_t stage, int kc, int tid,
                                     const __half* __restrict__ Whi) {
    const int k0 = kc * BK;
#pragma unroll
    for (int i = 0; i < 8; i++) {
        int g = tid + i * NTHREADS;     // 0..2047: 256 rows x 8 granules
        int row = g >> 3;
        int gb = g & 7;
        uint32_t off = sw128((uint32_t)(row * 128 + gb * 16));
        CPASYNC16(stage + B_HI + off, Whi + (size_t)row * HDIM + k0 + gb * 8);
    }
}

__device__ __forceinline__ void mma_stage(uint32_t stage, int n0w,
                                          int lid, float acc[4][4][4]) {
    const int lrow = (lid & 7) + ((lid >> 3) & 1) * 8;
    const int kb = ((lid >> 4) & 1) * 16;     // byte offset within row
#pragma unroll
    for (int ks = 0; ks < 4; ks++) {
        uint32_t ah[4][4];
#pragma unroll
        for (int mf = 0; mf < 4; mf++) {
            uint32_t off = sw128((uint32_t)((mf * 16 + lrow) * 128 + ks * 32 + kb));
            LDSM4(ah[mf][0], ah[mf][1], ah[mf][2], ah[mf][3], stage + A_HI + off);
        }
#pragma unroll
        for (int np = 0; np < 2; np++) {
            uint32_t boff = sw128((uint32_t)((n0w + np * 16 + lrow) * 128 + ks * 32 + kb));
            uint32_t bh0, bh1, bh2, bh3;
            LDSM4(bh0, bh1, bh2, bh3, stage + B_HI + boff);
#pragma unroll
            for (int mf = 0; mf < 4; mf++) {
                MMA16816(acc[mf][2 * np],     ah[mf], bh0, bh2);
                MMA16816(acc[mf][2 * np + 1], ah[mf], bh1, bh3);
            }
        }
    }
}

// -------------------------- main kernel ------------------------------------
// widx selects the weight set (0 = Us, 1 = Vs) via device-side symbol access.
template <bool GATHER>
__global__ void __launch_bounds__(NTHREADS, 2)
edgefeat_kernel(const float* __restrict__ A, int Mtot, int widx,
                const float* __restrict__ bias,
                const int* __restrict__ eidx, int Etot,
                float* __restrict__ out_g)
{
    extern __shared__ char smem_raw[];
    const uint32_t base = (smem_u32(smem_raw) + 1023u) & ~1023u;
    const uint32_t stg0 = base, stg1 = base + STAGE_BYTES;

    const __half* __restrict__ Whi = g_Whi[widx];   // device-side symbol ref

    const int tid = threadIdx.x;
    const int wid = tid >> 5;
    const int lid = tid & 31;
    const int m0 = blockIdx.x * BM;
    const int n0w = wid * 32;           // 8 warps cover N=256

    float acc[4][4][4];
#pragma unroll
    for (int a = 0; a < 4; a++)
#pragma unroll
        for (int b = 0; b < 4; b++)
#pragma unroll
            for (int c = 0; c < 4; c++) acc[a][b][c] = 0.f;

    float4 apf[4];

    // prologue: chunk 0
    prefetch_A(A, Mtot, m0, 0, tid, apf);
    cp_B(stg0, 0, tid, Whi);
    CP_COMMIT();
    sts_A(stg0, tid, apf);
    CP_WAIT0();
    __syncthreads();

#pragma unroll 1
    for (int kc = 0; kc < NCHUNK; kc++) {
        const uint32_t cur = (kc & 1) ? stg1 : stg0;
        const uint32_t nxt = (kc & 1) ? stg0 : stg1;
        if (kc + 1 < NCHUNK) {
            prefetch_A(A, Mtot, m0, kc + 1, tid, apf);
            cp_B(nxt, kc + 1, tid, Whi);
            CP_COMMIT();
        }
        mma_stage(cur, n0w, lid, acc);
        if (kc + 1 < NCHUNK) {
            sts_A(nxt, tid, apf);
            CP_WAIT0();
        }
        __syncthreads();
    }

    // epilogue: accs -> bias (+ fp16 gather) -> gmem
    const int tq = lid & 3;        // column-pair index
    const int trow = lid >> 2;     // 0..7
    float2 biasr[4];
#pragma unroll
    for (int nf = 0; nf < 4; nf++)
        biasr[nf] = *(const float2*)(bias + n0w + nf * 8 + 2 * tq);

#pragma unroll
    for (int mf = 0; mf < 4; mf++) {
#pragma unroll
        for (int h = 0; h < 2; h++) {
            const int row = m0 + mf * 16 + trow + 8 * h;
            if (row < Mtot) {
                if (GATHER) {
                    const __half* vs = g_Vx + (size_t)eidx[row] * HDIM;
                    const __half* vd = g_Vx + (size_t)eidx[(size_t)Etot + row] * HDIM;
                    float* op = out_g + (size_t)row * HDIM;
#pragma unroll
                    for (int nf = 0; nf < 4; nf++) {
                        const int c = n0w + nf * 8 + 2 * tq;
                        float2 s2 = __half22float2(*(const __half2*)(vs + c));
                        float2 d2 = __half22float2(*(const __half2*)(vd + c));
                        float vx = acc[mf][nf][2 * h + 0] + biasr[nf].x + s2.x + d2.x;
                        float vy = acc[mf][nf][2 * h + 1] + biasr[nf].y + s2.y + d2.y;
                        *(float2*)(op + c) = make_float2(vx, vy);
                    }
                } else {
                    __half* op = g_Vx + (size_t)row * HDIM;
#pragma unroll
                    for (int nf = 0; nf < 4; nf++) {
                        const int c = n0w + nf * 8 + 2 * tq;
                        float vx = acc[mf][nf][2 * h + 0] + biasr[nf].x;
                        float vy = acc[mf][nf][2 * h + 1] + biasr[nf].y;
                        *(__half2*)(op + c) = __floats2half2_rn(vx, vy);
                    }
                }
            }
        }
    }
}

// -------------------------- launch -----------------------------------------
extern "C" void kernel_launch(void* const* d_in, const int* in_sizes, int n_in,
                              void* d_out, int out_size) {
    const float* x    = (const float*)d_in[0];
    const float* e    = (const float*)d_in[1];
    const int*   eidx = (const int*)d_in[2];      // int32! (JAX x64 disabled)
    const float* Us_w = (const float*)d_in[3];
    const float* Us_b = (const float*)d_in[4];
    const float* Vs_w = (const float*)d_in[5];
    const float* Vs_b = (const float*)d_in[6];
    float*       out  = (float*)d_out;

    const int V = in_sizes[0] / HDIM;   // 10000
    const int E = in_sizes[1] / HDIM;   // 300000

    cudaFuncSetAttribute(edgefeat_kernel<false>,
                         cudaFuncAttributeMaxDynamicSharedMemorySize, SMEM_ALLOC);
    cudaFuncSetAttribute(edgefeat_kernel<true>,
                         cudaFuncAttributeMaxDynamicSharedMemorySize, SMEM_ALLOC);

    convert_weights_kernel<<<256, 256>>>(Us_w, Vs_w);

    // Vx = x @ Vs_w^T + Vs_b  -> g_Vx (fp16)   (weight set 1)
    edgefeat_kernel<false><<<(V + BM - 1) / BM, NTHREADS, SMEM_ALLOC>>>(
        x, V, 1, Vs_b, nullptr, 0, nullptr);

    // out = e @ Us_w^T + Us_b + Vx[src] + Vx[dst]   (weight set 0)
    edgefeat_kernel<true><<<(E + BM - 1) / BM, NTHREADS, SMEM_ALLOC>>>(
        e, E, 0, Us_b, eidx, E, out);
}